// round 9
// baseline (speedup 1.0000x reference)
#include <cuda_runtime.h>
#include <cstdint>

#define BATCH 512
#define TLEN  8192
#define DTC   1e-3f
#define NWARP 8
#define NTHR  (NWARP * 32)     // 256
#define LS    2                // steps per lane
#define TILE  (NTHR * LS)      // 512
#define NTILE (TLEN / TILE)    // 16

// self = self ∘ prev (prev applied first)
__device__ __forceinline__ void compose(float& M00, float& M01, float& M10, float& M11,
                                        float& v0, float& v1,
                                        float pM00, float pM01, float pM10, float pM11,
                                        float pv0, float pv1) {
    float n00 = M00 * pM00 + M01 * pM10;
    float n01 = M00 * pM01 + M01 * pM11;
    float n10 = M10 * pM00 + M11 * pM10;
    float n11 = M10 * pM01 + M11 * pM11;
    float nv0 = M00 * pv0 + M01 * pv1 + v0;
    float nv1 = M10 * pv0 + M11 * pv1 + v1;
    M00 = n00; M01 = n01; M10 = n10; M11 = n11; v0 = nv0; v1 = nv1;
}

__device__ __forceinline__ void step_transform(float4 q, float dx, float dy_,
                                               float a00, float a01, float a10, float a11,
                                               float c00, float c01, float c10, float c11,
                                               float& T00, float& T01, float& T10, float& T11,
                                               float& b0, float& b1) {
    T00 = 1.0f + DTC * (a00 - (q.x * c00 + q.y * c10));
    T01 =        DTC * (a01 - (q.x * c01 + q.y * c11));
    T10 =        DTC * (a10 - (q.z * c00 + q.w * c10));
    T11 = 1.0f + DTC * (a11 - (q.z * c01 + q.w * c11));
    b0  = q.x * dx + q.y * dy_;
    b1  = q.z * dx + q.w * dy_;
}

// ---------------- Fused direct-load kernel, 1 barrier per tile ----------------
__global__ __launch_bounds__(NTHR, 4)
void kFused(const float4* __restrict__ xic, const float4* __restrict__ dyv4,
            const float* __restrict__ Ac, const float* __restrict__ Cm,
            float4* __restrict__ out4) {
    __shared__ float4 wcs[NWARP][2];   // per-warp composite: [0]=M rows, [1]=(v0,v1,_,_)
    __shared__ float2 carry[2];        // tile-entry state, parity double-buffered

    const int tid  = threadIdx.x;
    const int lane = tid & 31;
    const int w    = tid >> 5;
    const int b    = blockIdx.x;

    const float c00 = __ldg(Cm + 0), c01 = __ldg(Cm + 1), c10 = __ldg(Cm + 2), c11 = __ldg(Cm + 3);
    const float a00 = __ldg(Ac + 0), a01 = __ldg(Ac + 1), a10 = __ldg(Ac + 2), a11 = __ldg(Ac + 3);

    if (tid == 0) carry[0] = make_float2(1.0f, 0.0f);
    // visibility of carry[0] guaranteed by tile 0's __syncthreads below

    const size_t rowbase = (size_t)b * TLEN;
    const int s0 = w * 64 + lane * 2;             // this thread's first step within a tile

    const float4* xp = xic  + rowbase + s0;
    const float4* dp = dyv4 + (rowbase >> 1) + (s0 >> 1);
    float4*       op = out4 + (rowbase >> 1) + (s0 >> 1);

    // prologue: load tile 0
    float4 q0  = __ldg(xp);
    float4 q1  = __ldg(xp + 1);
    float4 d01 = __ldg(dp);                       // (d0.x, d0.y, d1.x, d1.y)

    for (int tile = 0; tile < NTILE; tile++) {
        // --- transforms for this tile (consume q0,q1,d01) ---
        float T00, T01, T10, T11, B00, B01;       // step 0
        float U00, U01, U10, U11, B10, B11;       // step 1
        step_transform(q0, d01.x, d01.y, a00, a01, a10, a11, c00, c01, c10, c11,
                       T00, T01, T10, T11, B00, B01);
        step_transform(q1, d01.z, d01.w, a00, a01, a10, a11, c00, c01, c10, c11,
                       U00, U01, U10, U11, B10, B11);

        // --- prefetch next tile into now-dead registers ---
        if (tile + 1 < NTILE) {
            const float4* xn = xp + (tile + 1) * TILE;
            const float4* dn = dp + (tile + 1) * (TILE / 2);
            q0  = __ldg(xn);
            q1  = __ldg(xn + 1);
            d01 = __ldg(dn);
        }

        // lane composite = U ∘ T
        float M00 = U00 * T00 + U01 * T10;
        float M01 = U00 * T01 + U01 * T11;
        float M10 = U10 * T00 + U11 * T10;
        float M11 = U10 * T01 + U11 * T11;
        float v0  = U00 * B00 + U01 * B01 + B10;
        float v1  = U10 * B00 + U11 * B01 + B11;

        // --- warp inclusive scan ---
        #pragma unroll
        for (int d = 1; d < 32; d <<= 1) {
            float pM00 = __shfl_up_sync(0xffffffffu, M00, d);
            float pM01 = __shfl_up_sync(0xffffffffu, M01, d);
            float pM10 = __shfl_up_sync(0xffffffffu, M10, d);
            float pM11 = __shfl_up_sync(0xffffffffu, M11, d);
            float pv0  = __shfl_up_sync(0xffffffffu, v0,  d);
            float pv1  = __shfl_up_sync(0xffffffffu, v1,  d);
            if (lane >= d) compose(M00, M01, M10, M11, v0, v1, pM00, pM01, pM10, pM11, pv0, pv1);
        }

        if (lane == 31) {
            wcs[w][0] = make_float4(M00, M01, M10, M11);
            wcs[w][1] = make_float4(v0, v1, 0.f, 0.f);
        }
        __syncthreads();   // the ONLY barrier per tile: wcs + carry[tile&1] visible

        // --- lane 0 of each warp: propagate state through preceding warp composites ---
        float xw0, xw1;
        if (lane == 0) {
            float2 c = carry[tile & 1];
            float cx0 = c.x, cx1 = c.y;
            for (int i = 0; i < w; i++) {
                float4 Mw = wcs[i][0];
                float4 vw = wcs[i][1];
                float nx0 = Mw.x * cx0 + Mw.y * cx1 + vw.x;
                float nx1 = Mw.z * cx0 + Mw.w * cx1 + vw.y;
                cx0 = nx0; cx1 = nx1;
            }
            xw0 = cx0; xw1 = cx1;
            if (w == NWARP - 1) {
                // produce next tile's entry state (consumed after NEXT barrier)
                float4 Mw = wcs[NWARP - 1][0];
                float4 vw = wcs[NWARP - 1][1];
                carry[(tile + 1) & 1] = make_float2(Mw.x * cx0 + Mw.y * cx1 + vw.x,
                                                    Mw.z * cx0 + Mw.w * cx1 + vw.y);
            }
        }
        xw0 = __shfl_sync(0xffffffffu, xw0, 0);
        xw1 = __shfl_sync(0xffffffffu, xw1, 0);

        // --- exclusive lane prefix, apply to warp start state ---
        float pM00 = __shfl_up_sync(0xffffffffu, M00, 1);
        float pM01 = __shfl_up_sync(0xffffffffu, M01, 1);
        float pM10 = __shfl_up_sync(0xffffffffu, M10, 1);
        float pM11 = __shfl_up_sync(0xffffffffu, M11, 1);
        float pv0  = __shfl_up_sync(0xffffffffu, v0,  1);
        float pv1  = __shfl_up_sync(0xffffffffu, v1,  1);
        if (lane == 0) { pM00 = 1.f; pM01 = 0.f; pM10 = 0.f; pM11 = 1.f; pv0 = 0.f; pv1 = 0.f; }

        float x0 = pM00 * xw0 + pM01 * xw1 + pv0;
        float x1 = pM10 * xw0 + pM11 * xw1 + pv1;

        // --- replay 2 steps from register transforms; one coalesced float4 store ---
        float4 o;
        o.x = DTC * (c00 * x0 + c01 * x1);
        o.y = DTC * (c10 * x0 + c11 * x1);
        {
            float nx0 = T00 * x0 + T01 * x1 + B00;
            float nx1 = T10 * x0 + T11 * x1 + B01;
            x0 = nx0; x1 = nx1;
        }
        o.z = DTC * (c00 * x0 + c01 * x1);
        o.w = DTC * (c10 * x0 + c11 * x1);

        op[tile * (TILE / 2)] = o;
        // wcs for next tile is written pre-next-barrier by lane31 only after its
        // own scan completes; reads of this tile's wcs (lane 0 chain) happen
        // before that warp's lane31 can reach the next write? NO ordering issue:
        // lane31's next write is in the same warp as lane0's reads -> warp-
        // synchronous shfl_sync above orders them; cross-warp writes are fenced
        // by the next __syncthreads.
    }
}

extern "C" void kernel_launch(void* const* d_in, const int* in_sizes, int n_in,
                              void* d_out, int out_size) {
    const float4* xic  = (const float4*)d_in[0];  // [B,T,2,2] f32
    const float4* dyv4 = (const float4*)d_in[1];  // [B,T,2]   f32, float4 = 2 steps
    const float*  Ac   = (const float*)d_in[2];   // [2,2]
    const float*  Cm   = (const float*)d_in[3];   // [2,2]
    float4* out4 = (float4*)d_out;                // [B,T,2] viewed as float4 pairs

    kFused<<<BATCH, NTHR>>>(xic, dyv4, Ac, Cm, out4);
}